// round 10
// baseline (speedup 1.0000x reference)
#include <cuda_runtime.h>
#include <math.h>

#define B_DIM 128
#define TDIM 8192
#define NFEAT 32
#define MS 16
#define NEAR_END 6553       // int(8192*0.8); mask is P > NEAR_END

#define NTH 256
#define CTAS_PER_ROW 16
#define WORK_CTAS (B_DIM * CTAS_PER_ROW)   // 2048
#define GRID (WORK_CTAS + B_DIM)           // 2176
#define ROW_T4 (TDIM / 4)                  // 2048 t4-units per row
#define TILE 2048
#define TCH 8                              // per-thread chunk within a tile

// ---- device scratch --------------------------------------------------------
__device__ float g_mean[B_DIM * TDIM];     // 4 MB per-timestep means
__device__ int   g_row_done[B_DIM];

// ============================================================================
// Prologue: reset readiness flags (graph-replay safe).
// ============================================================================
__global__ void zero_flags()
{
    if (threadIdx.x < B_DIM) g_row_done[threadIdx.x] = 0;
}

// ============================================================================
// Fused kernel.
//  bid < 2048 : worker — stream 1/16 of row (bid/16)'s x into per-t means.
//  bid >= 2048: scorer — wait for row's 16 workers, then scan+bf+softmax.
// ============================================================================
__global__ __launch_bounds__(NTH)
void fused_kernel(const float4* __restrict__ x4,
                  const float* __restrict__ prior_mean,
                  const float* __restrict__ prior_var,
                  const float* __restrict__ noise_var,
                  float* __restrict__ out)
{
    __shared__ float4 sbuf[TDIM / 4];   // 32 KB means staging (scorers only)
    __shared__ float  ws1[8], ws2[8];
    __shared__ float  mg_m[8], mg_a[8], mg_k[8];

    const int tid  = threadIdx.x;
    const int lane = tid & 31;
    const int warp = tid >> 5;
    const int bid  = blockIdx.x;

    // ======================= WORKER PATH ===================================
    if (bid < WORK_CTAS) {
        const int r = bid >> 4;
        const int c = bid & 15;
        const int wrow = c * 8 + warp;           // 0..127 warp-slot in row
        const size_t rowt4 = (size_t)r * ROW_T4;

        #pragma unroll
        for (int it = 0; it < 2; ++it) {
            float4 v[8];
            float  s[8];
            #pragma unroll
            for (int k = 0; k < 8; ++k) {
                const size_t t4 = rowt4 + wrow + (size_t)(it * 8 + k) * 128;
                v[k] = __ldcs(&x4[t4 * 32 + lane]);
            }
            #pragma unroll
            for (int k = 0; k < 8; ++k)
                s[k] = (v[k].x + v[k].y) + (v[k].z + v[k].w);
            #pragma unroll
            for (int d = 1; d < 8; d <<= 1) {
                #pragma unroll
                for (int k = 0; k < 8; ++k)
                    s[k] += __shfl_xor_sync(0xffffffffu, s[k], d);
            }
            if ((lane & 7) == 0) {
                const int rr = lane >> 3;
                #pragma unroll
                for (int k = 0; k < 8; ++k) {
                    const size_t t4 = rowt4 + wrow + (size_t)(it * 8 + k) * 128;
                    g_mean[t4 * 4 + rr] = s[k] * (1.0f / NFEAT);
                }
            }
        }
        __syncthreads();
        __threadfence();
        if (tid == 0) atomicAdd(&g_row_done[r], 1);
        return;
    }

    // ======================= SCORER PATH ===================================
    const int r = bid - WORK_CTAS;

    if (tid == 0) {
        int v;
        do {
            asm volatile("ld.acquire.gpu.b32 %0, [%1];"
                         : "=r"(v) : "l"(&g_row_done[r]) : "memory");
            if (v != CTAS_PER_ROW) __nanosleep(128);
        } while (v != CTAS_PER_ROW);
    }
    __syncthreads();

    // ---- stage this row's means into SMEM (coalesced, L2-path) ---------------
    const float4* mrow4 = reinterpret_cast<const float4*>(g_mean + (size_t)r * TDIM);
    #pragma unroll
    for (int i = 0; i < 8; ++i)
        sbuf[tid + i * NTH] = __ldcg(&mrow4[tid + i * NTH]);
    __syncthreads();

    // ---- row totals (strided, conflict-free) ---------------------------------
    float t1 = 0.f, t2 = 0.f;
    #pragma unroll
    for (int i = 0; i < 8; ++i) {
        float4 v = sbuf[tid + i * NTH];
        t1 += (v.x + v.y) + (v.z + v.w);
        t2 += (v.x * v.x + v.y * v.y) + (v.z * v.z + v.w * v.w);
    }
    #pragma unroll
    for (int d = 16; d > 0; d >>= 1) {
        t1 += __shfl_xor_sync(0xffffffffu, t1, d);
        t2 += __shfl_xor_sync(0xffffffffu, t2, d);
    }
    if (lane == 0) { ws1[warp] = t1; ws2[warp] = t2; }
    __syncthreads();
    float totS = 0.f, totQ = 0.f;
    #pragma unroll
    for (int w = 0; w < 8; ++w) { totS += ws1[w]; totQ += ws2[w]; }
    __syncthreads();   // ws reused by tile scans below

    // ---- row constants -------------------------------------------------------
    const float pm = prior_mean[0];
    const float pv = log1pf(expf(prior_var[0]));
    const float nv = log1pf(expf(noise_var[0]));
    const float inv_pv = 1.0f / pv;
    const float inv_nv = 1.0f / nv;
    const float pmipv  = pm * inv_pv;
    const float pm2pv  = pm * pm * inv_pv;

    const float nW = (float)TDIM;
    const float aW = inv_pv + nW * inv_nv;
    const float rcp_aW = 1.0f / aW;
    const float btW = pmipv + totS * inv_nv;
    const float s2nW = totS * totS / nW;
    const float vW = fmaxf((totQ - s2nW) / (nW - 1.0f), 1e-8f);
    const float K = 0.5f * ((nW * vW + s2nW) * inv_nv - btW * btW * rcp_aW - pm2pv);
    const float nhalf_inv_nv = -0.5f * inv_nv;
    const float cpv = pv * rcp_aW;

    // ---- 4 sequential tiles: scan + bf + online softmax ----------------------
    float carry1 = 0.f, carry2 = 0.f;
    float om = -INFINITY, sa = 0.f, sm = 0.f;

    for (int tile = 0; tile < 4; ++tile) {
        float loc[TCH];
        float c1 = 0.f, c2 = 0.f;
        #pragma unroll
        for (int q = 0; q < TCH / 4; ++q) {
            float4 v = sbuf[tile * (TILE / 4) + tid * 2 + q];
            loc[q * 4 + 0] = v.x; loc[q * 4 + 1] = v.y;
            loc[q * 4 + 2] = v.z; loc[q * 4 + 3] = v.w;
            c1 += (v.x + v.y) + (v.z + v.w);
            c2 += (v.x * v.x + v.y * v.y) + (v.z * v.z + v.w * v.w);
        }
        // warp inclusive scan of chunk sums
        float i1 = c1, i2 = c2;
        #pragma unroll
        for (int d = 1; d < 32; d <<= 1) {
            float a = __shfl_up_sync(0xffffffffu, i1, d);
            float bb = __shfl_up_sync(0xffffffffu, i2, d);
            if (lane >= d) { i1 += a; i2 += bb; }
        }
        if (lane == 31) { ws1[warp] = i1; ws2[warp] = i2; }
        __syncthreads();
        // serial 8-warp offsets + tile totals (deterministic order)
        float off1 = 0.f, off2 = 0.f, tt1 = 0.f, tt2 = 0.f;
        #pragma unroll
        for (int w = 0; w < 8; ++w) {
            if (w < warp) { off1 += ws1[w]; off2 += ws2[w]; }
            tt1 += ws1[w]; tt2 += ws2[w];
        }
        float a = carry1 + off1 + (i1 - c1);   // exclusive prefix at chunk start
        float q = carry2 + off2 + (i2 - c2);

        const int basep = tile * TILE + tid * TCH;
        #pragma unroll
        for (int j = 0; j < TCH; ++j) {
            const int P = basep + j;
            const float mv = loc[j];
            const bool valid = (P >= MS) && (P < TDIM - MS);

            const float fL = (float)P;
            const float fR = nW - fL;

            const float rLL = __fdividef(1.0f, fL * (fL - 1.0f));
            const float rL   = rLL * (fL - 1.0f);
            const float rLm1 = rLL * fL;
            const float rRR = __fdividef(1.0f, fR * (fR - 1.0f));
            const float rR   = rRR * (fR - 1.0f);
            const float rRm1 = rRR * fR;

            const float sL = a, qL = q;
            const float sR = totS - sL, qR = totQ - qL;

            const float s2L = sL * sL * rL;
            const float vL  = fmaxf((qL - s2L) * rLm1, 1e-8f);
            const float s2R = sR * sR * rR;
            const float vR  = fmaxf((qR - s2R) * rRm1, 1e-8f);
            const float sumv = (fL * vL + s2L) + (fR * vR + s2R);

            const float aL = inv_pv + fL * inv_nv;
            const float aR = inv_pv + fR * inv_nv;
            const float btL = pmipv + sL * inv_nv;
            const float btR = pmipv + sR * inv_nv;
            const float rprod = __fdividef(1.0f, aL * aR);
            const float quad = (btL * btL * aR + btR * btR * aL) * rprod;

            const float bf = -0.5f * __logf(cpv * aL * aR)
                             + fmaf(nhalf_inv_nv, sumv, 0.5f * quad) + K;

            if (valid) {
                const float msk = (P > NEAR_END) ? 1.0f : 0.0f;
                if (bf <= om) {
                    const float e = __expf(bf - om);
                    sa += e; sm += msk * e;
                } else {
                    const float sc = __expf(om - bf);   // exp(-inf)=0 on first hit
                    sa = sa * sc + 1.0f;
                    sm = sm * sc + msk;
                    om = bf;
                }
            }
            a += mv;
            q += mv * mv;
        }
        carry1 += tt1;
        carry2 += tt2;
        __syncthreads();   // protect ws before next tile overwrites
    }

    // ---- merge (om, sa, sm) across threads -----------------------------------
    #pragma unroll
    for (int d = 16; d > 0; d >>= 1) {
        const float om2 = __shfl_xor_sync(0xffffffffu, om, d);
        const float sa2 = __shfl_xor_sync(0xffffffffu, sa, d);
        const float sm2 = __shfl_xor_sync(0xffffffffu, sm, d);
        if (om2 > om) {
            const float sc = __expf(om - om2);
            sa = sa * sc + sa2; sm = sm * sc + sm2; om = om2;
        } else {
            const float sc = __expf(om2 - om);
            sa += sa2 * sc; sm += sm2 * sc;
        }
    }
    if (lane == 0) { mg_m[warp] = om; mg_a[warp] = sa; mg_k[warp] = sm; }
    __syncthreads();
    if (tid == 0) {
        float M = mg_m[0], A = mg_a[0], S = mg_k[0];
        #pragma unroll
        for (int w = 1; w < 8; ++w) {
            const float om2 = mg_m[w], sa2 = mg_a[w], sm2 = mg_k[w];
            if (om2 > M) {
                const float sc = __expf(M - om2);
                A = A * sc + sa2; S = S * sc + sm2; M = om2;
            } else {
                const float sc = __expf(om2 - M);
                A += sa2 * sc; S += sm2 * sc;
            }
        }
        const float conf = 1.0f / (1.0f + __expf(-M));
        out[r] = conf * (S / A);
    }
}

extern "C" void kernel_launch(void* const* d_in, const int* in_sizes, int n_in,
                              void* d_out, int out_size)
{
    const float4* x4 = (const float4*)d_in[0];
    const float* pm = (const float*)d_in[1];
    const float* pv = (const float*)d_in[2];
    const float* nv = (const float*)d_in[3];
    float* out = (float*)d_out;
    zero_flags<<<1, 128>>>();
    fused_kernel<<<GRID, NTH>>>(x4, pm, pv, nv, out);
}

// round 11
// speedup vs baseline: 1.0055x; 1.0055x over previous
#include <cuda_runtime.h>
#include <math.h>

#define B_DIM 128
#define TDIM 8192
#define NFEAT 32
#define MS 16
#define NEAR_END 6553       // int(8192*0.8); mask is P > NEAR_END

#define NTH 256
#define CTAS_PER_ROW 16
#define WORK_CTAS (B_DIM * CTAS_PER_ROW)   // 2048
#define GRID (WORK_CTAS + B_DIM)           // 2176
#define ROW_T4 (TDIM / 4)                  // 2048 t4-units per row
#define TILE 2048
#define TCH 8                              // per-thread chunk within a tile

// ---- device scratch --------------------------------------------------------
__device__ float g_mean[B_DIM * TDIM];     // 4 MB per-timestep means
__device__ int   g_row_done[B_DIM];

// ============================================================================
// Prologue: reset readiness flags (graph-replay safe).
// ============================================================================
__global__ void zero_flags()
{
    if (threadIdx.x < B_DIM) g_row_done[threadIdx.x] = 0;
}

// ============================================================================
// Fused kernel.
//  bid < 2048 : worker — stream 1/16 of row (bid/16)'s x into per-t means.
//  bid >= 2048: scorer — wait for row's 16 workers, then scan+bf+softmax.
// ============================================================================
__global__ __launch_bounds__(NTH)
void fused_kernel(const float4* __restrict__ x4,
                  const float* __restrict__ prior_mean,
                  const float* __restrict__ prior_var,
                  const float* __restrict__ noise_var,
                  float* __restrict__ out)
{
    __shared__ float4 sbuf[TDIM / 4];   // 32 KB means staging (scorers only)
    __shared__ float  ws1[8], ws2[8];
    __shared__ float  mg_m[8], mg_a[8], mg_k[8];

    const int tid  = threadIdx.x;
    const int lane = tid & 31;
    const int warp = tid >> 5;
    const int bid  = blockIdx.x;

    // ======================= WORKER PATH ===================================
    if (bid < WORK_CTAS) {
        const int r = bid >> 4;
        const int c = bid & 15;
        const int wrow = c * 8 + warp;           // 0..127 warp-slot in row
        const size_t rowt4 = (size_t)r * ROW_T4;

        #pragma unroll
        for (int it = 0; it < 2; ++it) {
            float4 v[8];
            float  s[8];
            #pragma unroll
            for (int k = 0; k < 8; ++k) {
                const size_t t4 = rowt4 + wrow + (size_t)(it * 8 + k) * 128;
                v[k] = __ldcs(&x4[t4 * 32 + lane]);
            }
            #pragma unroll
            for (int k = 0; k < 8; ++k)
                s[k] = (v[k].x + v[k].y) + (v[k].z + v[k].w);
            #pragma unroll
            for (int d = 1; d < 8; d <<= 1) {
                #pragma unroll
                for (int k = 0; k < 8; ++k)
                    s[k] += __shfl_xor_sync(0xffffffffu, s[k], d);
            }
            if ((lane & 7) == 0) {
                const int rr = lane >> 3;
                #pragma unroll
                for (int k = 0; k < 8; ++k) {
                    const size_t t4 = rowt4 + wrow + (size_t)(it * 8 + k) * 128;
                    g_mean[t4 * 4 + rr] = s[k] * (1.0f / NFEAT);
                }
            }
        }
        __syncthreads();
        __threadfence();
        if (tid == 0) atomicAdd(&g_row_done[r], 1);
        return;
    }

    // ======================= SCORER PATH ===================================
    const int r = bid - WORK_CTAS;

    if (tid == 0) {
        int v;
        do {
            asm volatile("ld.acquire.gpu.b32 %0, [%1];"
                         : "=r"(v) : "l"(&g_row_done[r]) : "memory");
            if (v != CTAS_PER_ROW) __nanosleep(128);
        } while (v != CTAS_PER_ROW);
    }
    __syncthreads();

    // ---- stage this row's means into SMEM (coalesced, L2-path) ---------------
    const float4* mrow4 = reinterpret_cast<const float4*>(g_mean + (size_t)r * TDIM);
    #pragma unroll
    for (int i = 0; i < 8; ++i)
        sbuf[tid + i * NTH] = __ldcg(&mrow4[tid + i * NTH]);
    __syncthreads();

    // ---- row totals (strided, conflict-free) ---------------------------------
    float t1 = 0.f, t2 = 0.f;
    #pragma unroll
    for (int i = 0; i < 8; ++i) {
        float4 v = sbuf[tid + i * NTH];
        t1 += (v.x + v.y) + (v.z + v.w);
        t2 += (v.x * v.x + v.y * v.y) + (v.z * v.z + v.w * v.w);
    }
    #pragma unroll
    for (int d = 16; d > 0; d >>= 1) {
        t1 += __shfl_xor_sync(0xffffffffu, t1, d);
        t2 += __shfl_xor_sync(0xffffffffu, t2, d);
    }
    if (lane == 0) { ws1[warp] = t1; ws2[warp] = t2; }
    __syncthreads();
    float totS = 0.f, totQ = 0.f;
    #pragma unroll
    for (int w = 0; w < 8; ++w) { totS += ws1[w]; totQ += ws2[w]; }
    __syncthreads();   // ws reused by tile scans below

    // ---- row constants -------------------------------------------------------
    const float pm = prior_mean[0];
    const float pv = log1pf(expf(prior_var[0]));
    const float nv = log1pf(expf(noise_var[0]));
    const float inv_pv = 1.0f / pv;
    const float inv_nv = 1.0f / nv;
    const float pmipv  = pm * inv_pv;
    const float pm2pv  = pm * pm * inv_pv;

    const float nW = (float)TDIM;
    const float aW = inv_pv + nW * inv_nv;
    const float rcp_aW = 1.0f / aW;
    const float btW = pmipv + totS * inv_nv;
    const float s2nW = totS * totS / nW;
    const float vW = fmaxf((totQ - s2nW) / (nW - 1.0f), 1e-8f);
    const float K = 0.5f * ((nW * vW + s2nW) * inv_nv - btW * btW * rcp_aW - pm2pv);
    const float nhalf_inv_nv = -0.5f * inv_nv;
    const float cpv = pv * rcp_aW;

    // ---- 4 sequential tiles: scan + bf + online softmax ----------------------
    float carry1 = 0.f, carry2 = 0.f;
    float om = -INFINITY, sa = 0.f, sm = 0.f;

    for (int tile = 0; tile < 4; ++tile) {
        float loc[TCH];
        float c1 = 0.f, c2 = 0.f;
        #pragma unroll
        for (int q = 0; q < TCH / 4; ++q) {
            float4 v = sbuf[tile * (TILE / 4) + tid * 2 + q];
            loc[q * 4 + 0] = v.x; loc[q * 4 + 1] = v.y;
            loc[q * 4 + 2] = v.z; loc[q * 4 + 3] = v.w;
            c1 += (v.x + v.y) + (v.z + v.w);
            c2 += (v.x * v.x + v.y * v.y) + (v.z * v.z + v.w * v.w);
        }
        // warp inclusive scan of chunk sums
        float i1 = c1, i2 = c2;
        #pragma unroll
        for (int d = 1; d < 32; d <<= 1) {
            float a = __shfl_up_sync(0xffffffffu, i1, d);
            float bb = __shfl_up_sync(0xffffffffu, i2, d);
            if (lane >= d) { i1 += a; i2 += bb; }
        }
        if (lane == 31) { ws1[warp] = i1; ws2[warp] = i2; }
        __syncthreads();
        // serial 8-warp offsets + tile totals (deterministic order)
        float off1 = 0.f, off2 = 0.f, tt1 = 0.f, tt2 = 0.f;
        #pragma unroll
        for (int w = 0; w < 8; ++w) {
            if (w < warp) { off1 += ws1[w]; off2 += ws2[w]; }
            tt1 += ws1[w]; tt2 += ws2[w];
        }
        float a = carry1 + off1 + (i1 - c1);   // exclusive prefix at chunk start
        float q = carry2 + off2 + (i2 - c2);

        const int basep = tile * TILE + tid * TCH;
        #pragma unroll
        for (int j = 0; j < TCH; ++j) {
            const int P = basep + j;
            const float mv = loc[j];
            const bool valid = (P >= MS) && (P < TDIM - MS);

            const float fL = (float)P;
            const float fR = nW - fL;

            const float rLL = __fdividef(1.0f, fL * (fL - 1.0f));
            const float rL   = rLL * (fL - 1.0f);
            const float rLm1 = rLL * fL;
            const float rRR = __fdividef(1.0f, fR * (fR - 1.0f));
            const float rR   = rRR * (fR - 1.0f);
            const float rRm1 = rRR * fR;

            const float sL = a, qL = q;
            const float sR = totS - sL, qR = totQ - qL;

            const float s2L = sL * sL * rL;
            const float vL  = fmaxf((qL - s2L) * rLm1, 1e-8f);
            const float s2R = sR * sR * rR;
            const float vR  = fmaxf((qR - s2R) * rRm1, 1e-8f);
            const float sumv = (fL * vL + s2L) + (fR * vR + s2R);

            const float aL = inv_pv + fL * inv_nv;
            const float aR = inv_pv + fR * inv_nv;
            const float btL = pmipv + sL * inv_nv;
            const float btR = pmipv + sR * inv_nv;
            const float rprod = __fdividef(1.0f, aL * aR);
            const float quad = (btL * btL * aR + btR * btR * aL) * rprod;

            const float bf = -0.5f * __logf(cpv * aL * aR)
                             + fmaf(nhalf_inv_nv, sumv, 0.5f * quad) + K;

            if (valid) {
                const float msk = (P > NEAR_END) ? 1.0f : 0.0f;
                if (bf <= om) {
                    const float e = __expf(bf - om);
                    sa += e; sm += msk * e;
                } else {
                    const float sc = __expf(om - bf);   // exp(-inf)=0 on first hit
                    sa = sa * sc + 1.0f;
                    sm = sm * sc + msk;
                    om = bf;
                }
            }
            a += mv;
            q += mv * mv;
        }
        carry1 += tt1;
        carry2 += tt2;
        __syncthreads();   // protect ws before next tile overwrites
    }

    // ---- merge (om, sa, sm) across threads -----------------------------------
    #pragma unroll
    for (int d = 16; d > 0; d >>= 1) {
        const float om2 = __shfl_xor_sync(0xffffffffu, om, d);
        const float sa2 = __shfl_xor_sync(0xffffffffu, sa, d);
        const float sm2 = __shfl_xor_sync(0xffffffffu, sm, d);
        if (om2 > om) {
            const float sc = __expf(om - om2);
            sa = sa * sc + sa2; sm = sm * sc + sm2; om = om2;
        } else {
            const float sc = __expf(om2 - om);
            sa += sa2 * sc; sm += sm2 * sc;
        }
    }
    if (lane == 0) { mg_m[warp] = om; mg_a[warp] = sa; mg_k[warp] = sm; }
    __syncthreads();
    if (tid == 0) {
        float M = mg_m[0], A = mg_a[0], S = mg_k[0];
        #pragma unroll
        for (int w = 1; w < 8; ++w) {
            const float om2 = mg_m[w], sa2 = mg_a[w], sm2 = mg_k[w];
            if (om2 > M) {
                const float sc = __expf(M - om2);
                A = A * sc + sa2; S = S * sc + sm2; M = om2;
            } else {
                const float sc = __expf(om2 - M);
                A += sa2 * sc; S += sm2 * sc;
            }
        }
        const float conf = 1.0f / (1.0f + __expf(-M));
        out[r] = conf * (S / A);
    }
}

extern "C" void kernel_launch(void* const* d_in, const int* in_sizes, int n_in,
                              void* d_out, int out_size)
{
    const float4* x4 = (const float4*)d_in[0];
    const float* pm = (const float*)d_in[1];
    const float* pv = (const float*)d_in[2];
    const float* nv = (const float*)d_in[3];
    float* out = (float*)d_out;
    zero_flags<<<1, 128>>>();
    fused_kernel<<<GRID, NTH>>>(x4, pm, pv, nv, out);
}